// round 7
// baseline (speedup 1.0000x reference)
#include <cuda_runtime.h>

// Permutation: x[B=16, C=64, H=256, W=256] fp32
//   out[b][i][j][k][cc][hh][ww] = x[b][i*32+cc][j*16+hh][k*16+ww]
//
// Round 7: 2-channel tiles. CTA = (b, i, ccp, j) where ccp = cc>>1.
//   reads : two 16 KB contiguous runs (channels 2*ccp, 2*ccp+1)
//   writes: 16 chunks of 2 KB contiguous (c2 occupies output bit 6)
// j in the low grid bits -> co-resident CTAs read adjacent 16 KB tiles.
// SMEM [c2][hh][k*4+ww4] rows padded 64->68 f4: conflict-free 128-bit
// STS (warp-linear) and LDS (phases alternate word halves mod 32 banks).

static constexpr unsigned NBLOCKS = 16u * 2u * 16u * 16u;  // (b,i,ccp,j) = 8192

__global__ __launch_bounds__(256)
void reshape_78271484002964_kernel(const float4* __restrict__ in,
                                   float4* __restrict__ out) {
    __shared__ float4 sm[2 * 16 * 68];  // 34816 B

    unsigned bid = blockIdx.x;
    unsigned j   = bid & 15u;           // low bits: adjacent CTAs -> adjacent reads
    unsigned ccp = (bid >> 4) & 15u;
    unsigned i   = (bid >> 8) & 1u;
    unsigned b   = bid >> 9;

    unsigned ch0 = (b << 6) + (i << 5) + (ccp << 1);
    const float4* src0 = in + (ch0 << 14) + (j << 10);
    const float4* src1 = src0 + (1u << 14);

    unsigned t = threadIdx.x;

    // ---- Phase 1: stream 2 x 16 KB contiguous input (front-batched) ----
    float4 a0 = __ldcs(src0 + t);
    float4 a1 = __ldcs(src0 + t + 256u);
    float4 a2 = __ldcs(src0 + t + 512u);
    float4 a3 = __ldcs(src0 + t + 768u);
    float4 b0 = __ldcs(src1 + t);
    float4 b1 = __ldcs(src1 + t + 256u);
    float4 b2 = __ldcs(src1 + t + 512u);
    float4 b3 = __ldcs(src1 + t + 768u);

    // input-linear offset o: hh = o>>6, kw = o&63 ; smem = c2*1088 + hh*68 + kw
    unsigned s0 = ((t        ) >> 6) * 68u + ((t        ) & 63u);
    unsigned s1 = ((t + 256u ) >> 6) * 68u + ((t + 256u ) & 63u);
    unsigned s2 = ((t + 512u ) >> 6) * 68u + ((t + 512u ) & 63u);
    unsigned s3 = ((t + 768u ) >> 6) * 68u + ((t + 768u ) & 63u);
    sm[s0]          = a0; sm[s1]          = a1;
    sm[s2]          = a2; sm[s3]          = a3;
    sm[s0 + 1088u]  = b0; sm[s1 + 1088u]  = b1;
    sm[s2 + 1088u]  = b2; sm[s3 + 1088u]  = b3;

    __syncthreads();

    // ---- Phase 2: emit in output order ----
    // out f4 idx = ww4 | hh<<2 | cc<<6 | k<<11 | j<<15 | i<<19 | b<<20
    //            = ww4 | hh<<2 | c2<<6 | ccp<<7 | k<<11 | ...
    unsigned out_base = (ccp << 7) + (j << 15) + (i << 19) + (b << 20);

#pragma unroll
    for (unsigned it = 0; it < 8u; ++it) {
        unsigned p   = t + it * 256u;    // output-linear offset in 2048-f4 tile
        unsigned k   = p >> 7;
        unsigned rem = p & 127u;         // c2<<6 | hh<<2 | ww4
        unsigned c2  = rem >> 6;
        unsigned hh  = (rem >> 2) & 15u;
        unsigned ww4 = rem & 3u;
        float4 v = sm[c2 * 1088u + hh * 68u + (k << 2) + ww4];
        __stcs(&out[out_base + (k << 11) + rem], v);
    }
}

extern "C" void kernel_launch(void* const* d_in, const int* in_sizes, int n_in,
                              void* d_out, int out_size) {
    const float4* in  = (const float4*)d_in[0];
    float4*       out = (float4*)d_out;

    reshape_78271484002964_kernel<<<NBLOCKS, 256>>>(in, out);
}

// round 8
// speedup vs baseline: 1.1494x; 1.1494x over previous
#include <cuda_runtime.h>

// Permutation: x[B=16, C=64, H=256, W=256] fp32
//   out[b][i][j][k][cc][hh][ww] = x[b][i*32+cc][j*16+hh][k*16+ww]
//
// Round 8: R6 structure (16KB tile, 17KB padded smem, one barrier, occ ~92%)
// with HYBRID CTA ordering: low 2 bits = cc (co-scheduled CTAs write ADJACENT
// 1KB chunks -> 4KB contiguous write runs per k), next 4 bits = j (adjacent
// 16KB read tiles within each group). Both DRAM streams get multi-KB
// same-direction run length from the resident cohort.
// SMEM rows padded 64->68 f4: conflict-free 128-bit STS and LDS.

static constexpr unsigned NBLOCKS = 16u * 2u * 32u * 16u;  // 16384

__global__ __launch_bounds__(256)
void reshape_78271484002964_kernel(const float4* __restrict__ in,
                                   float4* __restrict__ out) {
    __shared__ float4 sm[16 * 68];  // [hh][k*4+ww4 padded to 68] = 17408 B

    unsigned bid  = blockIdx.x;
    unsigned c_lo = bid & 3u;            // write adjacency (out bit 6..7)
    unsigned j    = (bid >> 2) & 15u;    // read adjacency (adjacent 16KB tiles)
    unsigned c_hi = (bid >> 6) & 7u;
    unsigned i    = (bid >> 9) & 1u;
    unsigned b    = bid >> 10;
    unsigned cc   = (c_hi << 2) | c_lo;

    unsigned channel = (b << 6) + (i << 5) + cc;
    const float4* src = in + (channel << 14) + (j << 10);

    unsigned t = threadIdx.x;

    // ---- Phase 1: stream 16 KB contiguous input (front-batched) ----
    float4 v0 = __ldcs(src + t);
    float4 v1 = __ldcs(src + t + 256u);
    float4 v2 = __ldcs(src + t + 512u);
    float4 v3 = __ldcs(src + t + 768u);

    // input-linear offset o: hh = o>>6, kw = o&63 ; smem addr = hh*68 + kw
    sm[((t        ) >> 6) * 68u + ((t        ) & 63u)] = v0;
    sm[((t + 256u ) >> 6) * 68u + ((t + 256u ) & 63u)] = v1;
    sm[((t + 512u ) >> 6) * 68u + ((t + 512u ) & 63u)] = v2;
    sm[((t + 768u ) >> 6) * 68u + ((t + 768u ) & 63u)] = v3;

    __syncthreads();

    // ---- Phase 2: emit in output order ----
    // out f4 idx = ww4 | hh<<2 | cc<<6 | k<<11 | j<<15 | i<<19 | b<<20
    unsigned out_base = (cc << 6) + (j << 15) + (i << 19) + (b << 20);

#pragma unroll
    for (unsigned it = 0; it < 4u; ++it) {
        unsigned p   = t + it * 256u;        // output-linear offset in tile
        unsigned ww4 = p & 3u;
        unsigned hh  = (p >> 2) & 15u;
        unsigned k   = p >> 6;
        float4 v = sm[hh * 68u + (k << 2) + ww4];
        __stcs(&out[out_base + (k << 11) + (p & 63u)], v);
    }
}

extern "C" void kernel_launch(void* const* d_in, const int* in_sizes, int n_in,
                              void* d_out, int out_size) {
    const float4* in  = (const float4*)d_in[0];
    float4*       out = (float4*)d_out;

    reshape_78271484002964_kernel<<<NBLOCKS, 256>>>(in, out);
}